// round 9
// baseline (speedup 1.0000x reference)
#include <cuda_runtime.h>
#include <math.h>

#define BB 256
#define N_SV 64
#define N_TRK 512
#define N_PFC 512
#define KNN 8
#define HH 32

typedef unsigned long long u64;
typedef unsigned int u32;

// ---------------- scratch (static device arrays; no allocation) -------------
__device__ float g_sv [BB * N_SV  * HH];
__device__ float g_trk[BB * N_TRK * HH];
__device__ float g_pfc[BB * N_PFC * HH];
__device__ float g_U  [BB * N_TRK * HH];
__device__ float g_V  [BB * N_PFC * HH];
__device__ float g_V1 [BB * N_SV  * HH];
__device__ float g_f1 [BB * N_TRK * HH];
__device__ float g_f2 [BB * N_TRK * HH];
__device__ float g_f3 [BB * N_TRK * HH];

__device__ __forceinline__ float eluf(float x) {
    return x > 0.f ? x : (expf(x) - 1.f);
}

__device__ __forceinline__ void tf32split(float x, u32& h, u32& l) {
    asm("cvt.rna.tf32.f32 %0, %1;" : "=r"(h) : "f"(x));
    float r = x - __uint_as_float(h);
    asm("cvt.rna.tf32.f32 %0, %1;" : "=r"(l) : "f"(r));
}

__device__ __forceinline__ void mma_tf32(float& c0, float& c1, float& c2, float& c3,
                                         u32 a0, u32 a1, u32 a2, u32 a3,
                                         u32 b0, u32 b1)
{
    asm volatile(
        "mma.sync.aligned.m16n8k8.row.col.f32.tf32.tf32.f32 "
        "{%0,%1,%2,%3}, {%4,%5,%6,%7}, {%8,%9}, {%0,%1,%2,%3};"
        : "+f"(c0), "+f"(c1), "+f"(c2), "+f"(c3)
        : "r"(a0), "r"(a1), "r"(a2), "r"(a3), "r"(b0), "r"(b1));
}

// sorted ascending insert into 8-entry u64 list (sel[7] = worst kept)
#define SEL_INSERT(sel, c)                                          \
    if ((c) < sel[7]) {                                             \
        sel[7] = (c);                                               \
        _Pragma("unroll")                                           \
        for (int _p = 7; _p > 0; --_p) {                            \
            if (sel[_p] < sel[_p - 1]) {                            \
                u64 _t = sel[_p]; sel[_p] = sel[_p-1]; sel[_p-1] = _t; \
            }                                                       \
        }                                                           \
    }

// ================= fused encoder: 2-layer MLP, 128 nodes/block ==============
template <int FIN>
__device__ __forceinline__ void encode_body(
    const float* __restrict__ x,
    const float* __restrict__ W1, const float* __restrict__ b1,
    const float* __restrict__ W2, const float* __restrict__ b2,
    float* __restrict__ out, int blk,
    float* w1s, float* w2s, float* b1s, float* b2s)
{
    int tid = threadIdx.x;
    for (int i = tid; i < FIN * 32; i += 256) w1s[i] = W1[i];
    for (int i = tid; i < 1024;     i += 256) w2s[i] = W2[i];
    if (tid < 32) { b1s[tid] = b1[tid]; b2s[tid] = b2[tid]; }
    __syncthreads();

    int lane = tid & 31, wid = tid >> 5;

#pragma unroll
    for (int it = 0; it < 4; ++it) {
        int nb = blk * 128 + it * 32 + wid * 4;

        float xv0 = (lane < FIN) ? x[(size_t)(nb + 0) * FIN + lane] : 0.f;
        float xv1 = (lane < FIN) ? x[(size_t)(nb + 1) * FIN + lane] : 0.f;
        float xv2 = (lane < FIN) ? x[(size_t)(nb + 2) * FIN + lane] : 0.f;
        float xv3 = (lane < FIN) ? x[(size_t)(nb + 3) * FIN + lane] : 0.f;

        float h0 = b1s[lane], h1 = h0, h2 = h0, h3 = h0;
#pragma unroll
        for (int i = 0; i < FIN; ++i) {
            float w = w1s[i * 32 + lane];
            h0 = fmaf(__shfl_sync(0xffffffffu, xv0, i), w, h0);
            h1 = fmaf(__shfl_sync(0xffffffffu, xv1, i), w, h1);
            h2 = fmaf(__shfl_sync(0xffffffffu, xv2, i), w, h2);
            h3 = fmaf(__shfl_sync(0xffffffffu, xv3, i), w, h3);
        }
        h0 = eluf(h0); h1 = eluf(h1); h2 = eluf(h2); h3 = eluf(h3);

        float o0 = b2s[lane], o1 = o0, o2 = o0, o3 = o0;
#pragma unroll
        for (int i = 0; i < 32; ++i) {
            float w = w2s[i * 32 + lane];
            o0 = fmaf(__shfl_sync(0xffffffffu, h0, i), w, o0);
            o1 = fmaf(__shfl_sync(0xffffffffu, h1, i), w, o1);
            o2 = fmaf(__shfl_sync(0xffffffffu, h2, i), w, o2);
            o3 = fmaf(__shfl_sync(0xffffffffu, h3, i), w, o3);
        }
        out[(size_t)(nb + 0) * 32 + lane] = eluf(o0);
        out[(size_t)(nb + 1) * 32 + lane] = eluf(o1);
        out[(size_t)(nb + 2) * 32 + lane] = eluf(o2);
        out[(size_t)(nb + 3) * 32 + lane] = eluf(o3);
    }
}

__global__ void __launch_bounds__(256) encode_all_k(
    const float* x_sv, const float* x_trk, const float* x_pfc,
    const float* svW1, const float* svb1, const float* svW2, const float* svb2,
    const float* tkW1, const float* tkb1, const float* tkW2, const float* tkb2,
    const float* pfW1, const float* pfb1, const float* pfW2, const float* pfb2,
    float* o_sv, float* o_trk, float* o_pfc)
{
    __shared__ float w1s[32 * 32];
    __shared__ float w2s[32 * 32];
    __shared__ float b1s[32], b2s[32];
    int b = blockIdx.x;
    if (b < 128)
        encode_body<14>(x_sv, svW1, svb1, svW2, svb2, o_sv, b, w1s, w2s, b1s, b2s);
    else if (b < 1152)
        encode_body<30>(x_trk, tkW1, tkb1, tkW2, tkb2, o_trk, b - 128, w1s, w2s, b1s, b2s);
    else
        encode_body<10>(x_pfc, pfW1, pfb1, pfW2, pfb2, o_pfc, b - 1152, w1s, w2s, b1s, b2s);
}

// ================ fused 32x32 linear (mode 0: (Wa-Wb)+b, mode 1: Wb) ========
__device__ __forceinline__ void lin_body(
    const float* __restrict__ in, float* __restrict__ out, int blk, int mode,
    const float* __restrict__ convW, const float* __restrict__ convB,
    float* ws, float* bs)
{
    int tid = threadIdx.x;
    for (int i = tid; i < 1024; i += 256)
        ws[i] = (mode == 0) ? (convW[i] - convW[1024 + i]) : convW[1024 + i];
    if (tid < 32) bs[tid] = (mode == 0) ? convB[tid] : 0.f;
    __syncthreads();

    int lane = tid & 31, wid = tid >> 5;

#pragma unroll
    for (int it = 0; it < 4; ++it) {
        int nb = blk * 128 + it * 32 + wid * 4;

        float xv0 = in[(size_t)(nb + 0) * 32 + lane];
        float xv1 = in[(size_t)(nb + 1) * 32 + lane];
        float xv2 = in[(size_t)(nb + 2) * 32 + lane];
        float xv3 = in[(size_t)(nb + 3) * 32 + lane];
        float o0 = bs[lane], o1 = o0, o2 = o0, o3 = o0;
#pragma unroll
        for (int i = 0; i < 32; ++i) {
            float w = ws[i * 32 + lane];
            o0 = fmaf(__shfl_sync(0xffffffffu, xv0, i), w, o0);
            o1 = fmaf(__shfl_sync(0xffffffffu, xv1, i), w, o1);
            o2 = fmaf(__shfl_sync(0xffffffffu, xv2, i), w, o2);
            o3 = fmaf(__shfl_sync(0xffffffffu, xv3, i), w, o3);
        }
        out[(size_t)(nb + 0) * 32 + lane] = o0;
        out[(size_t)(nb + 1) * 32 + lane] = o1;
        out[(size_t)(nb + 2) * 32 + lane] = o2;
        out[(size_t)(nb + 3) * 32 + lane] = o3;
    }
}

__global__ void __launch_bounds__(256) lin_all_k(
    const float* sv, const float* trk, const float* pfc,
    float* V1, float* U, float* V,
    const float* convW, const float* convB)
{
    __shared__ float ws[1024];
    __shared__ float bs[32];
    int b = blockIdx.x;
    if (b < 128)        lin_body(sv,  V1, b,        1, convW, convB, ws, bs);
    else if (b < 1152)  lin_body(trk, U,  b - 128,  0, convW, convB, ws, bs);
    else                lin_body(pfc, V,  b - 1152, 1, convW, convB, ws, bs);
}

__global__ void __launch_bounds__(256) lin2_k(
    const float* f1, const float* f2, float* V, float* U,
    const float* convW, const float* convB)
{
    __shared__ float ws[1024];
    __shared__ float bs[32];
    int b = blockIdx.x;
    if (b < 1024) lin_body(f1, V, b,        1, convW, convB, ws, bs);
    else          lin_body(f2, U, b - 1024, 0, convW, convB, ws, bs);
}

// ================= kNN: mma scoring -> smem scores -> scalar selection ======
// 4 blocks/event (128 dsts each), 256 threads = 8 warps, ONE m16 tile/warp
// (A-frags 32 regs -> no spills; smem ~70KB -> 3 CTAs/SM).
// MMA epilogue finalizes d2 into scores[128][67]. Selection: TWO threads per
// dst (even/odd interleaved columns), branch-free buffered appends, 2-way
// exact merge at the end. Candidate u64 = (f32bits(max(d2,0))<<32)|src_idx.
#define CH       64
#define STRIDE   67
#define CAPK     8
#define SM_SCORES 0
#define SM_HI    34304
#define SM_LO    (34304 + 9216)
#define SM_SQ    (34304 + 18432)
#define SM_SD    (SM_SQ + 256)
#define SM_BUF   (SM_SD + 512)
#define KNN_SMEM (SM_BUF + 256 * CAPK * 8)

__device__ __forceinline__ void flush_u64(const u64* mybuf, int& cnt, u64 (&sel)[8])
{
    for (int i = 0; i < cnt; ++i) {
        u64 c = mybuf[i];
        SEL_INSERT(sel, c);
    }
    cnt = 0;
}

__global__ void __launch_bounds__(256, 3) knn_k(
                      const float* __restrict__ src_enc,
                      const float* __restrict__ dst_enc,
                      const float* __restrict__ V,
                      const float* __restrict__ U,
                      float* __restrict__ out, int Ns)
{
    extern __shared__ char smraw[];
    float* scores  = (float*)(smraw + SM_SCORES);   // [128][67]
    float* srcT_hi = (float*)(smraw + SM_HI);       // [32][72]
    float* srcT_lo = (float*)(smraw + SM_LO);       // [32][72]
    float* sqs     = (float*)(smraw + SM_SQ);       // [64]
    float* sds     = (float*)(smraw + SM_SD);       // [128]
    u64*   buf     = (u64*)(smraw + SM_BUF);        // [256][CAPK]
    int*   idxs    = (int*)(smraw + SM_HI);         // overlay (after MMAs)

    int tid  = threadIdx.x;
    int lane = tid & 31;
    int w    = tid >> 5;          // 0..7
    int e    = blockIdx.x >> 2;
    int quar = blockIdx.x & 3;
    int g    = lane >> 2;         // 0..7
    int c4   = lane & 3;          // 0..3

    const float* sbase = src_enc + (size_t)e * Ns * 32;
    int dstblk = quar * 128;                       // event-local dst base
    const float* dbase = dst_enc + ((size_t)e * 512 + dstblk + w * 16) * 32;

    // ---- per-dst squared norms (threads 0..127) ----
    if (tid < 128) {
        const float4* myrow = (const float4*)(dst_enc + ((size_t)e * 512 + dstblk + tid) * 32);
        float s = 0.f;
#pragma unroll
        for (int q = 0; q < 8; ++q) {
            float4 v = myrow[q];
            s = fmaf(v.x, v.x, s); s = fmaf(v.y, v.y, s);
            s = fmaf(v.z, v.z, s); s = fmaf(v.w, v.w, s);
        }
        sds[tid] = s;
    }

    // ---- A fragments: one m16 tile (16 dsts) per warp ----
    u32 ahi[16], alo[16];
#pragma unroll
    for (int j = 0; j < 4; ++j) {
        int k = 8 * j + c4;
        tf32split(dbase[g * 32 + k],           ahi[4*j+0], alo[4*j+0]);
        tf32split(dbase[(g + 8) * 32 + k],     ahi[4*j+1], alo[4*j+1]);
        tf32split(dbase[g * 32 + k + 4],       ahi[4*j+2], alo[4*j+2]);
        tf32split(dbase[(g + 8) * 32 + k + 4], ahi[4*j+3], alo[4*j+3]);
    }
    __syncthreads();

    float sd0 = sds[w * 16 + g];
    float sd1 = sds[w * 16 + 8 + g];
    int rowA0 = (w * 16 + g) * STRIDE;
    int rowA1 = (w * 16 + 8 + g) * STRIDE;

    // selection identity: 2 threads per dst (even/odd columns)
    int myd = tid >> 1;
    int hh  = tid & 1;
    int selrow = myd * STRIDE;

    u64 sel[8];
#pragma unroll
    for (int k = 0; k < 8; ++k) sel[k] = ~0ull;
    int cnt = 0;
    u64* mybuf = buf + (size_t)tid * CAPK;
    unsigned buf_sa = (unsigned)__cvta_generic_to_shared(mybuf);

    int nch = (Ns + CH - 1) / CH;
    for (int ch = 0; ch < nch; ++ch) {
        int cbase = ch * CH;

        __syncthreads();
        // ---- stage 64 srcs: tf32-split transpose + squared norms ----
        for (int sl = w; sl < CH; sl += 8) {
            float x = sbase[(size_t)(cbase + sl) * 32 + lane];
            u32 h, l;
            tf32split(x, h, l);
            srcT_hi[lane * 72 + sl] = __uint_as_float(h);
            srcT_lo[lane * 72 + sl] = __uint_as_float(l);
            float v = x * x;
#pragma unroll
            for (int o = 16; o; o >>= 1) v += __shfl_xor_sync(0xffffffffu, v, o);
            if (lane == 0) sqs[sl] = v;
        }
        __syncthreads();

        // ---- MMA: 8 src-subtiles x 1 dst tile; finalize d2 into scores ----
#pragma unroll
        for (int st = 0; st < CH / 8; ++st) {
            int sl0 = st << 3;
            float a0 = 0.f, a1 = 0.f, a2 = 0.f, a3 = 0.f;
#pragma unroll
            for (int j = 0; j < 4; ++j) {
                int k = 8 * j + c4;
                int off = k * 72 + sl0 + g;
                u32 bh0 = __float_as_uint(srcT_hi[off]);
                u32 bh1 = __float_as_uint(srcT_hi[off + 4 * 72]);
                u32 bl0 = __float_as_uint(srcT_lo[off]);
                u32 bl1 = __float_as_uint(srcT_lo[off + 4 * 72]);
                mma_tf32(a0, a1, a2, a3, ahi[4*j+0], ahi[4*j+1], ahi[4*j+2], ahi[4*j+3], bh0, bh1);
                mma_tf32(a0, a1, a2, a3, ahi[4*j+0], ahi[4*j+1], ahi[4*j+2], ahi[4*j+3], bl0, bl1);
                mma_tf32(a0, a1, a2, a3, alo[4*j+0], alo[4*j+1], alo[4*j+2], alo[4*j+3], bh0, bh1);
            }
            float2 sqp = *(const float2*)(sqs + sl0 + 2 * c4);
            int col = sl0 + 2 * c4;
            scores[rowA0 + col]     = fmaxf(fmaf(-2.f, a0, sd0 + sqp.x), 0.f);
            scores[rowA0 + col + 1] = fmaxf(fmaf(-2.f, a1, sd0 + sqp.y), 0.f);
            scores[rowA1 + col]     = fmaxf(fmaf(-2.f, a2, sd1 + sqp.x), 0.f);
            scores[rowA1 + col + 1] = fmaxf(fmaf(-2.f, a3, sd1 + sqp.y), 0.f);
        }
        __syncthreads();

        // ---- selection: 2 threads/dst, interleaved cols, buffered appends --
        for (int cg = 0; cg < 32; cg += 4) {
            int c0i = 2 * cg + hh;
            float v0 = scores[selrow + c0i];
            float v1 = scores[selrow + c0i + 2];
            float v2 = scores[selrow + c0i + 4];
            float v3 = scores[selrow + c0i + 6];
            u64 p0 = ((u64)__float_as_uint(v0) << 32) | (u32)(cbase + c0i);
            u64 p1 = ((u64)__float_as_uint(v1) << 32) | (u32)(cbase + c0i + 2);
            u64 p2 = ((u64)__float_as_uint(v2) << 32) | (u32)(cbase + c0i + 4);
            u64 p3 = ((u64)__float_as_uint(v3) << 32) | (u32)(cbase + c0i + 6);

            asm volatile("{.reg .pred p; setp.lt.u64 p, %1, %2; @p st.shared.b64 [%0], %1;}"
                :: "r"(buf_sa + (unsigned)cnt * 8u), "l"(p0), "l"(sel[7]) : "memory");
            cnt += (p0 < sel[7]) ? 1 : 0;
            asm volatile("{.reg .pred p; setp.lt.u64 p, %1, %2; @p st.shared.b64 [%0], %1;}"
                :: "r"(buf_sa + (unsigned)cnt * 8u), "l"(p1), "l"(sel[7]) : "memory");
            cnt += (p1 < sel[7]) ? 1 : 0;
            asm volatile("{.reg .pred p; setp.lt.u64 p, %1, %2; @p st.shared.b64 [%0], %1;}"
                :: "r"(buf_sa + (unsigned)cnt * 8u), "l"(p2), "l"(sel[7]) : "memory");
            cnt += (p2 < sel[7]) ? 1 : 0;
            asm volatile("{.reg .pred p; setp.lt.u64 p, %1, %2; @p st.shared.b64 [%0], %1;}"
                :: "r"(buf_sa + (unsigned)cnt * 8u), "l"(p3), "l"(sel[7]) : "memory");
            cnt += (p3 < sel[7]) ? 1 : 0;

            if (__any_sync(0xffffffffu, cnt >= CAPK - 3)) {
                flush_u64(mybuf, cnt, sel);
            }
        }
    }
    flush_u64(mybuf, cnt, sel);

    // ---- dump per-thread lists (own region; no race), 2-way exact merge ----
#pragma unroll
    for (int k = 0; k < 8; ++k) mybuf[k] = sel[k];
    __syncthreads();

    if (tid < 128) {
        u64 m[8];
        const u64* l0 = buf + (size_t)(2 * tid) * CAPK;
        const u64* l1 = buf + (size_t)(2 * tid + 1) * CAPK;
#pragma unroll
        for (int k = 0; k < 8; ++k) m[k] = l0[k];
#pragma unroll
        for (int k = 0; k < 8; ++k) {
            u64 c = l1[k];
            SEL_INSERT(m, c);
        }
#pragma unroll
        for (int k = 0; k < 8; ++k)
            idxs[tid * 8 + k] = (int)(u32)m[k];
    }
    __syncthreads();

    // ---- aggregation: warp per dst, coalesced V gathers ----
    const float* Ve = V + (size_t)e * Ns * 32;
    for (int dd = w; dd < 128; dd += 8) {
        int dg = e * 512 + dstblk + dd;
        float mx = -3.4e38f;
#pragma unroll
        for (int k = 0; k < KNN; ++k) {
            int s = idxs[dd * 8 + k];
            mx = fmaxf(mx, Ve[s * 32 + lane]);
        }
        out[(size_t)dg * 32 + lane] = eluf(U[(size_t)dg * 32 + lane] + mx);
    }
}

// ---------------- mean pool + head MLP + sigmoid -----------------------------
__global__ void pool_k(const float* __restrict__ f3,
                       const float* __restrict__ W1, const float* __restrict__ b1,
                       const float* __restrict__ W2, const float* __restrict__ b2,
                       float* __restrict__ out, int out_size)
{
    int e = blockIdx.x;
    int tid = threadIdx.x;
    int j = tid & 31, g = tid >> 5;
    const float* base = f3 + (size_t)e * 512 * 32;
    float acc = 0.f;
    for (int r = g; r < 512; r += 8) acc += base[r * 32 + j];
    __shared__ float red[8][32];
    red[g][j] = acc;
    __syncthreads();
    if (tid < 32) {
        float s = 0.f;
#pragma unroll
        for (int gg = 0; gg < 8; ++gg) s += red[gg][tid];
        float pooled = s * (1.f / 512.f);
        float h = b1[tid];
#pragma unroll
        for (int i = 0; i < 32; ++i)
            h = fmaf(__shfl_sync(0xffffffffu, pooled, i), W1[i * 32 + tid], h);
        h = eluf(h);
        float t = h * W2[tid];
#pragma unroll
        for (int o = 16; o; o >>= 1) t += __shfl_down_sync(0xffffffffu, t, o);
        if (tid == 0) {
            float prob = 1.f / (1.f + expf(-(t + b2[0])));
            out[e] = prob;
            if (out_size == 2 * BB) out[BB + e] = (float)e;
            else if (out_size == 3 * BB) ((long long*)(out + BB))[e] = (long long)e;
        }
    }
}

// ---------------- launch ------------------------------------------------------
extern "C" void kernel_launch(void* const* d_in, const int* in_sizes, int n_in,
                              void* d_out, int out_size)
{
    const float* x_sv   = (const float*)d_in[0];
    const float* x_trk  = (const float*)d_in[1];
    const float* x_pfc  = (const float*)d_in[2];
    const float* sv_W1  = (const float*)d_in[6];
    const float* sv_b1  = (const float*)d_in[7];
    const float* sv_W2  = (const float*)d_in[8];
    const float* sv_b2  = (const float*)d_in[9];
    const float* trk_W1 = (const float*)d_in[10];
    const float* trk_b1 = (const float*)d_in[11];
    const float* trk_W2 = (const float*)d_in[12];
    const float* trk_b2 = (const float*)d_in[13];
    const float* pfc_W1 = (const float*)d_in[14];
    const float* pfc_b1 = (const float*)d_in[15];
    const float* pfc_W2 = (const float*)d_in[16];
    const float* pfc_b2 = (const float*)d_in[17];
    const float* conv_W = (const float*)d_in[18];
    const float* conv_b = (const float*)d_in[19];
    const float* out_W1 = (const float*)d_in[20];
    const float* out_b1 = (const float*)d_in[21];
    const float* out_W2 = (const float*)d_in[22];
    const float* out_b2 = (const float*)d_in[23];
    float* out = (float*)d_out;

    float *sv, *trk, *pfc, *U, *V, *V1, *f1, *f2, *f3;
    cudaGetSymbolAddress((void**)&sv,  g_sv);
    cudaGetSymbolAddress((void**)&trk, g_trk);
    cudaGetSymbolAddress((void**)&pfc, g_pfc);
    cudaGetSymbolAddress((void**)&U,   g_U);
    cudaGetSymbolAddress((void**)&V,   g_V);
    cudaGetSymbolAddress((void**)&V1,  g_V1);
    cudaGetSymbolAddress((void**)&f1,  g_f1);
    cudaGetSymbolAddress((void**)&f2,  g_f2);
    cudaGetSymbolAddress((void**)&f3,  g_f3);

    cudaFuncSetAttribute(knn_k, cudaFuncAttributeMaxDynamicSharedMemorySize, KNN_SMEM);

    encode_all_k<<<2176, 256>>>(x_sv, x_trk, x_pfc,
                                sv_W1, sv_b1, sv_W2, sv_b2,
                                trk_W1, trk_b1, trk_W2, trk_b2,
                                pfc_W1, pfc_b1, pfc_W2, pfc_b2,
                                sv, trk, pfc);
    lin_all_k<<<2176, 256>>>(sv, trk, pfc, V1, U, V, conv_W, conv_b);
    knn_k<<<BB * 4, 256, KNN_SMEM>>>(sv,  trk, V1, U, f1, N_SV);
    knn_k<<<BB * 4, 256, KNN_SMEM>>>(pfc, trk, V,  U, f2, N_PFC);
    lin2_k<<<2048, 256>>>(f1, f2, V, U, conv_W, conv_b);
    knn_k<<<BB * 4, 256, KNN_SMEM>>>(f1, f2, V, U, f3, N_TRK);
    pool_k<<<BB, 256>>>(f3, out_W1, out_b1, out_W2, out_b2, out, out_size);
}

// round 10
// speedup vs baseline: 1.0706x; 1.0706x over previous
#include <cuda_runtime.h>
#include <math.h>

#define BB 256
#define N_SV 64
#define N_TRK 512
#define N_PFC 512
#define KNN 8
#define HH 32

typedef unsigned long long u64;
typedef unsigned int u32;

// ---------------- scratch (static device arrays; no allocation) -------------
__device__ float g_sv [BB * N_SV  * HH];
__device__ float g_trk[BB * N_TRK * HH];
__device__ float g_pfc[BB * N_PFC * HH];
__device__ float g_U  [BB * N_TRK * HH];
__device__ float g_V  [BB * N_PFC * HH];
__device__ float g_V1 [BB * N_SV  * HH];
__device__ float g_f1 [BB * N_TRK * HH];
__device__ float g_f2 [BB * N_TRK * HH];
__device__ float g_f3 [BB * N_TRK * HH];
__device__ float g_sqV1[BB * N_SV ];
__device__ float g_sqV [BB * N_PFC];
__device__ float g_sqU [BB * N_TRK];

__device__ __forceinline__ float eluf(float x) {
    return x > 0.f ? x : (expf(x) - 1.f);
}

__device__ __forceinline__ void tf32split(float x, u32& h, u32& l) {
    asm("cvt.rna.tf32.f32 %0, %1;" : "=r"(h) : "f"(x));
    float r = x - __uint_as_float(h);
    asm("cvt.rna.tf32.f32 %0, %1;" : "=r"(l) : "f"(r));
}

__device__ __forceinline__ void mma_tf32(float& c0, float& c1, float& c2, float& c3,
                                         u32 a0, u32 a1, u32 a2, u32 a3,
                                         u32 b0, u32 b1)
{
    asm volatile(
        "mma.sync.aligned.m16n8k8.row.col.f32.tf32.tf32.f32 "
        "{%0,%1,%2,%3}, {%4,%5,%6,%7}, {%8,%9}, {%0,%1,%2,%3};"
        : "+f"(c0), "+f"(c1), "+f"(c2), "+f"(c3)
        : "r"(a0), "r"(a1), "r"(a2), "r"(a3), "r"(b0), "r"(b1));
}

// sorted ascending insert into 8-entry u64 list (sel[7] = worst kept)
#define SEL_INSERT(sel, c)                                          \
    if ((c) < sel[7]) {                                             \
        sel[7] = (c);                                               \
        _Pragma("unroll")                                           \
        for (int _p = 7; _p > 0; --_p) {                            \
            if (sel[_p] < sel[_p - 1]) {                            \
                u64 _t = sel[_p]; sel[_p] = sel[_p-1]; sel[_p-1] = _t; \
            }                                                       \
        }                                                           \
    }

// ================= fused encoder: 2-layer MLP, 128 nodes/block ==============
template <int FIN>
__device__ __forceinline__ void encode_body(
    const float* __restrict__ x,
    const float* __restrict__ W1, const float* __restrict__ b1,
    const float* __restrict__ W2, const float* __restrict__ b2,
    float* __restrict__ out, int blk,
    float* w1s, float* w2s, float* b1s, float* b2s)
{
    int tid = threadIdx.x;
    for (int i = tid; i < FIN * 32; i += 256) w1s[i] = W1[i];
    for (int i = tid; i < 1024;     i += 256) w2s[i] = W2[i];
    if (tid < 32) { b1s[tid] = b1[tid]; b2s[tid] = b2[tid]; }
    __syncthreads();

    int lane = tid & 31, wid = tid >> 5;

#pragma unroll
    for (int it = 0; it < 4; ++it) {
        int nb = blk * 128 + it * 32 + wid * 4;

        float xv0 = (lane < FIN) ? x[(size_t)(nb + 0) * FIN + lane] : 0.f;
        float xv1 = (lane < FIN) ? x[(size_t)(nb + 1) * FIN + lane] : 0.f;
        float xv2 = (lane < FIN) ? x[(size_t)(nb + 2) * FIN + lane] : 0.f;
        float xv3 = (lane < FIN) ? x[(size_t)(nb + 3) * FIN + lane] : 0.f;

        float h0 = b1s[lane], h1 = h0, h2 = h0, h3 = h0;
#pragma unroll
        for (int i = 0; i < FIN; ++i) {
            float w = w1s[i * 32 + lane];
            h0 = fmaf(__shfl_sync(0xffffffffu, xv0, i), w, h0);
            h1 = fmaf(__shfl_sync(0xffffffffu, xv1, i), w, h1);
            h2 = fmaf(__shfl_sync(0xffffffffu, xv2, i), w, h2);
            h3 = fmaf(__shfl_sync(0xffffffffu, xv3, i), w, h3);
        }
        h0 = eluf(h0); h1 = eluf(h1); h2 = eluf(h2); h3 = eluf(h3);

        float o0 = b2s[lane], o1 = o0, o2 = o0, o3 = o0;
#pragma unroll
        for (int i = 0; i < 32; ++i) {
            float w = w2s[i * 32 + lane];
            o0 = fmaf(__shfl_sync(0xffffffffu, h0, i), w, o0);
            o1 = fmaf(__shfl_sync(0xffffffffu, h1, i), w, o1);
            o2 = fmaf(__shfl_sync(0xffffffffu, h2, i), w, o2);
            o3 = fmaf(__shfl_sync(0xffffffffu, h3, i), w, o3);
        }
        out[(size_t)(nb + 0) * 32 + lane] = eluf(o0);
        out[(size_t)(nb + 1) * 32 + lane] = eluf(o1);
        out[(size_t)(nb + 2) * 32 + lane] = eluf(o2);
        out[(size_t)(nb + 3) * 32 + lane] = eluf(o3);
    }
}

__global__ void __launch_bounds__(256) encode_all_k(
    const float* x_sv, const float* x_trk, const float* x_pfc,
    const float* svW1, const float* svb1, const float* svW2, const float* svb2,
    const float* tkW1, const float* tkb1, const float* tkW2, const float* tkb2,
    const float* pfW1, const float* pfb1, const float* pfW2, const float* pfb2,
    float* o_sv, float* o_trk, float* o_pfc)
{
    __shared__ float w1s[32 * 32];
    __shared__ float w2s[32 * 32];
    __shared__ float b1s[32], b2s[32];
    int b = blockIdx.x;
    if (b < 128)
        encode_body<14>(x_sv, svW1, svb1, svW2, svb2, o_sv, b, w1s, w2s, b1s, b2s);
    else if (b < 1152)
        encode_body<30>(x_trk, tkW1, tkb1, tkW2, tkb2, o_trk, b - 128, w1s, w2s, b1s, b2s);
    else
        encode_body<10>(x_pfc, pfW1, pfb1, pfW2, pfb2, o_pfc, b - 1152, w1s, w2s, b1s, b2s);
}

// ====== fused 32x32 linear (mode 0: (Wa-Wb)+b, mode 1: Wb) + sq output ======
__device__ __forceinline__ void lin_body(
    const float* __restrict__ in, float* __restrict__ out,
    float* __restrict__ sqout, int blk, int mode,
    const float* __restrict__ convW, const float* __restrict__ convB,
    float* ws, float* bs)
{
    int tid = threadIdx.x;
    for (int i = tid; i < 1024; i += 256)
        ws[i] = (mode == 0) ? (convW[i] - convW[1024 + i]) : convW[1024 + i];
    if (tid < 32) bs[tid] = (mode == 0) ? convB[tid] : 0.f;
    __syncthreads();

    int lane = tid & 31, wid = tid >> 5;

#pragma unroll
    for (int it = 0; it < 4; ++it) {
        int nb = blk * 128 + it * 32 + wid * 4;

        float xv0 = in[(size_t)(nb + 0) * 32 + lane];
        float xv1 = in[(size_t)(nb + 1) * 32 + lane];
        float xv2 = in[(size_t)(nb + 2) * 32 + lane];
        float xv3 = in[(size_t)(nb + 3) * 32 + lane];

        // squared norms of the (encoded) inputs
        float s0 = xv0 * xv0, s1 = xv1 * xv1, s2 = xv2 * xv2, s3 = xv3 * xv3;
#pragma unroll
        for (int o = 16; o; o >>= 1) {
            s0 += __shfl_xor_sync(0xffffffffu, s0, o);
            s1 += __shfl_xor_sync(0xffffffffu, s1, o);
            s2 += __shfl_xor_sync(0xffffffffu, s2, o);
            s3 += __shfl_xor_sync(0xffffffffu, s3, o);
        }
        if (lane == 0) {
            sqout[nb + 0] = s0; sqout[nb + 1] = s1;
            sqout[nb + 2] = s2; sqout[nb + 3] = s3;
        }

        float o0 = bs[lane], o1 = o0, o2 = o0, o3 = o0;
#pragma unroll
        for (int i = 0; i < 32; ++i) {
            float w = ws[i * 32 + lane];
            o0 = fmaf(__shfl_sync(0xffffffffu, xv0, i), w, o0);
            o1 = fmaf(__shfl_sync(0xffffffffu, xv1, i), w, o1);
            o2 = fmaf(__shfl_sync(0xffffffffu, xv2, i), w, o2);
            o3 = fmaf(__shfl_sync(0xffffffffu, xv3, i), w, o3);
        }
        out[(size_t)(nb + 0) * 32 + lane] = o0;
        out[(size_t)(nb + 1) * 32 + lane] = o1;
        out[(size_t)(nb + 2) * 32 + lane] = o2;
        out[(size_t)(nb + 3) * 32 + lane] = o3;
    }
}

__global__ void __launch_bounds__(256) lin_all_k(
    const float* sv, const float* trk, const float* pfc,
    float* V1, float* U, float* V,
    float* sqV1, float* sqU, float* sqV,
    const float* convW, const float* convB)
{
    __shared__ float ws[1024];
    __shared__ float bs[32];
    int b = blockIdx.x;
    if (b < 128)        lin_body(sv,  V1, sqV1, b,        1, convW, convB, ws, bs);
    else if (b < 1152)  lin_body(trk, U,  sqU,  b - 128,  0, convW, convB, ws, bs);
    else                lin_body(pfc, V,  sqV,  b - 1152, 1, convW, convB, ws, bs);
}

__global__ void __launch_bounds__(256) lin2_k(
    const float* f1, const float* f2, float* V, float* U,
    float* sqV, float* sqU,
    const float* convW, const float* convB)
{
    __shared__ float ws[1024];
    __shared__ float bs[32];
    int b = blockIdx.x;
    if (b < 1024) lin_body(f1, V, sqV, b,        1, convW, convB, ws, bs);
    else          lin_body(f2, U, sqU, b - 1024, 0, convW, convB, ws, bs);
}

// ================= kNN: mma scoring + tau-threshold selection ===============
// 4 blocks/event (128 dsts), 256 threads = 8 warps, ONE m16 tile/warp.
// MMA epilogue: finalize d2 into scores[128][66] AND keep 2 float min-slots
// per dst-row per lane (8 disjoint-subset minima per row) -> tau = max of 8
// minima >= chunk 8th-smallest >= any global-top-8 member in this chunk.
// Selection: 2 threads/dst scan with FIXED threshold min(tau,sel7) -> pure
// predicated appends, one uniform flush per chunk. Exact & stable (u64 pack).
#define CH       64
#define SSTRIDE  66
#define HSTRIDE  68     /* u64 units per k-row of interleaved (hi,lo) */
#define CAPK     10
#define SM_SCORES 0
#define SM_HILO  33792
#define SM_SQS   51200
#define SM_SDS   51456
#define SM_TAU   51968
#define SM_BUF   52480
#define KNN_SMEM (SM_BUF + 256 * CAPK * 8)   /* 72960 */

__device__ __forceinline__ void flush_u64(const u64* mybuf, int& cnt, u64 (&sel)[8])
{
    for (int i = 0; i < cnt; ++i) {
        u64 c = mybuf[i];
        SEL_INSERT(sel, c);
    }
    cnt = 0;
}

__global__ void __launch_bounds__(256, 3) knn_k(
                      const float* __restrict__ src_enc,
                      const float* __restrict__ dst_enc,
                      const float* __restrict__ sq_src,
                      const float* __restrict__ sq_dst,
                      const float* __restrict__ V,
                      const float* __restrict__ U,
                      float* __restrict__ out, int Ns)
{
    extern __shared__ char smraw[];
    float* scores = (float*)(smraw + SM_SCORES);  // [128][66]
    u64*   hilo   = (u64*)(smraw + SM_HILO);      // [32][68] (hi,lo) pairs
    float* sqs    = (float*)(smraw + SM_SQS);     // [64]
    float* sds    = (float*)(smraw + SM_SDS);     // [128]
    float* tau    = (float*)(smraw + SM_TAU);     // [128]
    u64*   buf    = (u64*)(smraw + SM_BUF);       // [256][CAPK]
    int*   idxs   = (int*)(smraw + SM_HILO);      // overlay after last MMA

    int tid  = threadIdx.x;
    int lane = tid & 31;
    int w    = tid >> 5;          // 0..7
    int e    = blockIdx.x >> 2;
    int quar = blockIdx.x & 3;
    int g    = lane >> 2;         // 0..7
    int c4   = lane & 3;          // 0..3

    const float* sbase = src_enc + (size_t)e * Ns * 32;
    int dstblk = quar * 128;
    const float* dbase = dst_enc + ((size_t)e * 512 + dstblk + w * 16) * 32;

    // ---- dst squared norms: precomputed, one LDG ----
    if (tid < 128) sds[tid] = sq_dst[(size_t)e * 512 + dstblk + tid];

    // ---- A fragments: one m16 tile (16 dsts) per warp ----
    u32 ahi[16], alo[16];
#pragma unroll
    for (int j = 0; j < 4; ++j) {
        int k = 8 * j + c4;
        tf32split(dbase[g * 32 + k],           ahi[4*j+0], alo[4*j+0]);
        tf32split(dbase[(g + 8) * 32 + k],     ahi[4*j+1], alo[4*j+1]);
        tf32split(dbase[g * 32 + k + 4],       ahi[4*j+2], alo[4*j+2]);
        tf32split(dbase[(g + 8) * 32 + k + 4], ahi[4*j+3], alo[4*j+3]);
    }
    __syncthreads();

    float sd0 = sds[w * 16 + g];
    float sd1 = sds[w * 16 + 8 + g];
    int rowA0 = (w * 16 + g) * SSTRIDE;
    int rowA1 = (w * 16 + 8 + g) * SSTRIDE;

    int myd = tid >> 1;           // selection: 2 threads per dst
    int hh  = tid & 1;
    int selrow = myd * SSTRIDE;

    u64 sel[8];
#pragma unroll
    for (int k = 0; k < 8; ++k) sel[k] = ~0ull;
    int cnt = 0;
    u64* mybuf = buf + (size_t)tid * CAPK;
    unsigned buf_sa = (unsigned)__cvta_generic_to_shared(mybuf);

    int nch = (Ns + CH - 1) / CH;
    for (int ch = 0; ch < nch; ++ch) {
        int cbase = ch * CH;

        __syncthreads();
        // ---- stage 64 srcs: interleaved (hi,lo); sq via precomputed LDG ----
        for (int sl = w; sl < CH; sl += 8) {
            float x = sbase[(size_t)(cbase + sl) * 32 + lane];
            u32 h, l;
            tf32split(x, h, l);
            u64 p;
            asm("mov.b64 %0, {%1, %2};" : "=l"(p) : "r"(h), "r"(l));
            hilo[lane * HSTRIDE + sl] = p;
        }
        if (tid < CH) sqs[tid] = sq_src[(size_t)e * Ns + cbase + tid];
        __syncthreads();

        // ---- MMA + epilogue (scores + subset minima) ----
        float mn00 = 3.4e38f, mn01 = 3.4e38f, mn10 = 3.4e38f, mn11 = 3.4e38f;
#pragma unroll
        for (int st = 0; st < CH / 8; ++st) {
            int sl0 = st << 3;
            float a0 = 0.f, a1 = 0.f, a2 = 0.f, a3 = 0.f;
#pragma unroll
            for (int j = 0; j < 4; ++j) {
                int k = 8 * j + c4;
                u64 p0 = hilo[k * HSTRIDE + sl0 + g];
                u64 p1 = hilo[(k + 4) * HSTRIDE + sl0 + g];
                u32 bh0, bl0, bh1, bl1;
                asm("mov.b64 {%0, %1}, %2;" : "=r"(bh0), "=r"(bl0) : "l"(p0));
                asm("mov.b64 {%0, %1}, %2;" : "=r"(bh1), "=r"(bl1) : "l"(p1));
                mma_tf32(a0, a1, a2, a3, ahi[4*j+0], ahi[4*j+1], ahi[4*j+2], ahi[4*j+3], bh0, bh1);
                mma_tf32(a0, a1, a2, a3, ahi[4*j+0], ahi[4*j+1], ahi[4*j+2], ahi[4*j+3], bl0, bl1);
                mma_tf32(a0, a1, a2, a3, alo[4*j+0], alo[4*j+1], alo[4*j+2], alo[4*j+3], bh0, bh1);
            }
            float2 sqp = *(const float2*)(sqs + sl0 + 2 * c4);
            int col = sl0 + 2 * c4;
            float d00 = fmaxf(fmaf(-2.f, a0, sd0 + sqp.x), 0.f);
            float d01 = fmaxf(fmaf(-2.f, a1, sd0 + sqp.y), 0.f);
            float d10 = fmaxf(fmaf(-2.f, a2, sd1 + sqp.x), 0.f);
            float d11 = fmaxf(fmaf(-2.f, a3, sd1 + sqp.y), 0.f);
            mn00 = fminf(mn00, d00); mn01 = fminf(mn01, d01);
            mn10 = fminf(mn10, d10); mn11 = fminf(mn11, d11);
            *(float2*)(scores + rowA0 + col) = make_float2(d00, d01);
            *(float2*)(scores + rowA1 + col) = make_float2(d10, d11);
        }
        // tau per row: max over quad of the 2 slot-minima (8 disjoint subsets)
        {
            float m0 = fmaxf(mn00, mn01);
            m0 = fmaxf(m0, __shfl_xor_sync(0xffffffffu, m0, 1));
            m0 = fmaxf(m0, __shfl_xor_sync(0xffffffffu, m0, 2));
            float m1 = fmaxf(mn10, mn11);
            m1 = fmaxf(m1, __shfl_xor_sync(0xffffffffu, m1, 1));
            m1 = fmaxf(m1, __shfl_xor_sync(0xffffffffu, m1, 2));
            if (c4 == 0) {
                tau[w * 16 + g]     = m0;
                tau[w * 16 + 8 + g] = m1;
            }
        }
        __syncthreads();

        // ---- selection: fixed threshold, predicated appends ----
        {
            float tf_ = tau[myd];
            u64 tu = ((u64)(__float_as_uint(tf_) + 1u)) << 32;  // accept <= tau
            u64 t = (tu < sel[7]) ? tu : sel[7];

            for (int cg = 0; cg < 32; cg += 4) {
                int c0i = 2 * cg + hh;
                float v0 = scores[selrow + c0i];
                float v1 = scores[selrow + c0i + 2];
                float v2 = scores[selrow + c0i + 4];
                float v3 = scores[selrow + c0i + 6];
                u64 p0 = ((u64)__float_as_uint(v0) << 32) | (u32)(cbase + c0i);
                u64 p1 = ((u64)__float_as_uint(v1) << 32) | (u32)(cbase + c0i + 2);
                u64 p2 = ((u64)__float_as_uint(v2) << 32) | (u32)(cbase + c0i + 4);
                u64 p3 = ((u64)__float_as_uint(v3) << 32) | (u32)(cbase + c0i + 6);

                asm volatile("{.reg .pred p; setp.lt.u64 p, %1, %2; @p st.shared.b64 [%0], %1;}"
                    :: "r"(buf_sa + (unsigned)cnt * 8u), "l"(p0), "l"(t) : "memory");
                cnt += (p0 < t) ? 1 : 0;
                asm volatile("{.reg .pred p; setp.lt.u64 p, %1, %2; @p st.shared.b64 [%0], %1;}"
                    :: "r"(buf_sa + (unsigned)cnt * 8u), "l"(p1), "l"(t) : "memory");
                cnt += (p1 < t) ? 1 : 0;
                asm volatile("{.reg .pred p; setp.lt.u64 p, %1, %2; @p st.shared.b64 [%0], %1;}"
                    :: "r"(buf_sa + (unsigned)cnt * 8u), "l"(p2), "l"(t) : "memory");
                cnt += (p2 < t) ? 1 : 0;
                asm volatile("{.reg .pred p; setp.lt.u64 p, %1, %2; @p st.shared.b64 [%0], %1;}"
                    :: "r"(buf_sa + (unsigned)cnt * 8u), "l"(p3), "l"(t) : "memory");
                cnt += (p3 < t) ? 1 : 0;

                // safety flush (rare); keeps cnt <= CAPK-1
                if (__any_sync(0xffffffffu, cnt >= CAPK - 4)) {
                    flush_u64(mybuf, cnt, sel);
                }
            }
            flush_u64(mybuf, cnt, sel);   // per-chunk drain -> sel7 tightens
        }
    }

    // ---- dump per-thread lists, 2-way exact merge ----
#pragma unroll
    for (int k = 0; k < 8; ++k) mybuf[k] = sel[k];
    __syncthreads();

    if (tid < 128) {
        u64 m[8];
        const u64* l0 = buf + (size_t)(2 * tid) * CAPK;
        const u64* l1 = buf + (size_t)(2 * tid + 1) * CAPK;
#pragma unroll
        for (int k = 0; k < 8; ++k) m[k] = l0[k];
#pragma unroll
        for (int k = 0; k < 8; ++k) {
            u64 c = l1[k];
            SEL_INSERT(m, c);
        }
#pragma unroll
        for (int k = 0; k < 8; ++k)
            idxs[tid * 8 + k] = (int)(u32)m[k];
    }
    __syncthreads();

    // ---- aggregation: warp per dst, coalesced V gathers ----
    const float* Ve = V + (size_t)e * Ns * 32;
    for (int dd = w; dd < 128; dd += 8) {
        int dg = e * 512 + dstblk + dd;
        float mx = -3.4e38f;
#pragma unroll
        for (int k = 0; k < KNN; ++k) {
            int s = idxs[dd * 8 + k];
            mx = fmaxf(mx, Ve[s * 32 + lane]);
        }
        out[(size_t)dg * 32 + lane] = eluf(U[(size_t)dg * 32 + lane] + mx);
    }
}

// ---------------- mean pool + head MLP + sigmoid -----------------------------
__global__ void pool_k(const float* __restrict__ f3,
                       const float* __restrict__ W1, const float* __restrict__ b1,
                       const float* __restrict__ W2, const float* __restrict__ b2,
                       float* __restrict__ out, int out_size)
{
    int e = blockIdx.x;
    int tid = threadIdx.x;
    int j = tid & 31, g = tid >> 5;
    const float* base = f3 + (size_t)e * 512 * 32;
    float acc = 0.f;
    for (int r = g; r < 512; r += 8) acc += base[r * 32 + j];
    __shared__ float red[8][32];
    red[g][j] = acc;
    __syncthreads();
    if (tid < 32) {
        float s = 0.f;
#pragma unroll
        for (int gg = 0; gg < 8; ++gg) s += red[gg][tid];
        float pooled = s * (1.f / 512.f);
        float h = b1[tid];
#pragma unroll
        for (int i = 0; i < 32; ++i)
            h = fmaf(__shfl_sync(0xffffffffu, pooled, i), W1[i * 32 + tid], h);
        h = eluf(h);
        float t = h * W2[tid];
#pragma unroll
        for (int o = 16; o; o >>= 1) t += __shfl_down_sync(0xffffffffu, t, o);
        if (tid == 0) {
            float prob = 1.f / (1.f + expf(-(t + b2[0])));
            out[e] = prob;
            if (out_size == 2 * BB) out[BB + e] = (float)e;
            else if (out_size == 3 * BB) ((long long*)(out + BB))[e] = (long long)e;
        }
    }
}

// ---------------- launch ------------------------------------------------------
extern "C" void kernel_launch(void* const* d_in, const int* in_sizes, int n_in,
                              void* d_out, int out_size)
{
    const float* x_sv   = (const float*)d_in[0];
    const float* x_trk  = (const float*)d_in[1];
    const float* x_pfc  = (const float*)d_in[2];
    const float* sv_W1  = (const float*)d_in[6];
    const float* sv_b1  = (const float*)d_in[7];
    const float* sv_W2  = (const float*)d_in[8];
    const float* sv_b2  = (const float*)d_in[9];
    const float* trk_W1 = (const float*)d_in[10];
    const float* trk_b1 = (const float*)d_in[11];
    const float* trk_W2 = (const float*)d_in[12];
    const float* trk_b2 = (const float*)d_in[13];
    const float* pfc_W1 = (const float*)d_in[14];
    const float* pfc_b1 = (const float*)d_in[15];
    const float* pfc_W2 = (const float*)d_in[16];
    const float* pfc_b2 = (const float*)d_in[17];
    const float* conv_W = (const float*)d_in[18];
    const float* conv_b = (const float*)d_in[19];
    const float* out_W1 = (const float*)d_in[20];
    const float* out_b1 = (const float*)d_in[21];
    const float* out_W2 = (const float*)d_in[22];
    const float* out_b2 = (const float*)d_in[23];
    float* out = (float*)d_out;

    float *sv, *trk, *pfc, *U, *V, *V1, *f1, *f2, *f3, *sqV1, *sqV, *sqU;
    cudaGetSymbolAddress((void**)&sv,  g_sv);
    cudaGetSymbolAddress((void**)&trk, g_trk);
    cudaGetSymbolAddress((void**)&pfc, g_pfc);
    cudaGetSymbolAddress((void**)&U,   g_U);
    cudaGetSymbolAddress((void**)&V,   g_V);
    cudaGetSymbolAddress((void**)&V1,  g_V1);
    cudaGetSymbolAddress((void**)&f1,  g_f1);
    cudaGetSymbolAddress((void**)&f2,  g_f2);
    cudaGetSymbolAddress((void**)&f3,  g_f3);
    cudaGetSymbolAddress((void**)&sqV1, g_sqV1);
    cudaGetSymbolAddress((void**)&sqV,  g_sqV);
    cudaGetSymbolAddress((void**)&sqU,  g_sqU);

    cudaFuncSetAttribute(knn_k, cudaFuncAttributeMaxDynamicSharedMemorySize, KNN_SMEM);

    encode_all_k<<<2176, 256>>>(x_sv, x_trk, x_pfc,
                                sv_W1, sv_b1, sv_W2, sv_b2,
                                trk_W1, trk_b1, trk_W2, trk_b2,
                                pfc_W1, pfc_b1, pfc_W2, pfc_b2,
                                sv, trk, pfc);
    lin_all_k<<<2176, 256>>>(sv, trk, pfc, V1, U, V, sqV1, sqU, sqV, conv_W, conv_b);
    knn_k<<<BB * 4, 256, KNN_SMEM>>>(sv,  trk, sqV1, sqU, V1, U, f1, N_SV);
    knn_k<<<BB * 4, 256, KNN_SMEM>>>(pfc, trk, sqV,  sqU, V,  U, f2, N_PFC);
    lin2_k<<<2048, 256>>>(f1, f2, V, U, sqV, sqU, conv_W, conv_b);
    knn_k<<<BB * 4, 256, KNN_SMEM>>>(f1, f2, sqV, sqU, V, U, f3, N_TRK);
    pool_k<<<BB, 256>>>(f3, out_W1, out_b1, out_W2, out_b2, out, out_size);
}

// round 11
// speedup vs baseline: 1.0743x; 1.0035x over previous
#include <cuda_runtime.h>
#include <math.h>

#define BB 256
#define N_SV 64
#define N_TRK 512
#define N_PFC 512
#define KNN 8
#define HH 32

typedef unsigned long long u64;
typedef unsigned int u32;

// ---------------- scratch (static device arrays; no allocation) -------------
__device__ float g_sv [BB * N_SV  * HH];
__device__ float g_trk[BB * N_TRK * HH];
__device__ float g_pfc[BB * N_PFC * HH];
__device__ float g_U  [BB * N_TRK * HH];
__device__ float g_V  [BB * N_PFC * HH];
__device__ float g_V1 [BB * N_SV  * HH];
__device__ float g_f1 [BB * N_TRK * HH];
__device__ float g_f2 [BB * N_TRK * HH];
__device__ float g_f3 [BB * N_TRK * HH];
__device__ float g_sqV1[BB * N_SV ];
__device__ float g_sqV [BB * N_PFC];
__device__ float g_sqU [BB * N_TRK];

__device__ __forceinline__ float eluf(float x) {
    return x > 0.f ? x : (expf(x) - 1.f);
}

__device__ __forceinline__ void tf32split(float x, u32& h, u32& l) {
    asm("cvt.rna.tf32.f32 %0, %1;" : "=r"(h) : "f"(x));
    float r = x - __uint_as_float(h);
    asm("cvt.rna.tf32.f32 %0, %1;" : "=r"(l) : "f"(r));
}

__device__ __forceinline__ void mma_tf32(float& c0, float& c1, float& c2, float& c3,
                                         u32 a0, u32 a1, u32 a2, u32 a3,
                                         u32 b0, u32 b1)
{
    asm volatile(
        "mma.sync.aligned.m16n8k8.row.col.f32.tf32.tf32.f32 "
        "{%0,%1,%2,%3}, {%4,%5,%6,%7}, {%8,%9}, {%0,%1,%2,%3};"
        : "+f"(c0), "+f"(c1), "+f"(c2), "+f"(c3)
        : "r"(a0), "r"(a1), "r"(a2), "r"(a3), "r"(b0), "r"(b1));
}

// sorted ascending insert into 8-entry u64 list (sel[7] = worst kept)
#define SEL_INSERT(sel, c)                                          \
    if ((c) < sel[7]) {                                             \
        sel[7] = (c);                                               \
        _Pragma("unroll")                                           \
        for (int _p = 7; _p > 0; --_p) {                            \
            if (sel[_p] < sel[_p - 1]) {                            \
                u64 _t = sel[_p]; sel[_p] = sel[_p-1]; sel[_p-1] = _t; \
            }                                                       \
        }                                                           \
    }

// ================= fused encoder: 2-layer MLP, 128 nodes/block ==============
template <int FIN>
__device__ __forceinline__ void encode_body(
    const float* __restrict__ x,
    const float* __restrict__ W1, const float* __restrict__ b1,
    const float* __restrict__ W2, const float* __restrict__ b2,
    float* __restrict__ out, int blk,
    float* w1s, float* w2s, float* b1s, float* b2s)
{
    int tid = threadIdx.x;
    for (int i = tid; i < FIN * 32; i += 256) w1s[i] = W1[i];
    for (int i = tid; i < 1024;     i += 256) w2s[i] = W2[i];
    if (tid < 32) { b1s[tid] = b1[tid]; b2s[tid] = b2[tid]; }
    __syncthreads();

    int lane = tid & 31, wid = tid >> 5;

#pragma unroll
    for (int it = 0; it < 4; ++it) {
        int nb = blk * 128 + it * 32 + wid * 4;

        float xv0 = (lane < FIN) ? x[(size_t)(nb + 0) * FIN + lane] : 0.f;
        float xv1 = (lane < FIN) ? x[(size_t)(nb + 1) * FIN + lane] : 0.f;
        float xv2 = (lane < FIN) ? x[(size_t)(nb + 2) * FIN + lane] : 0.f;
        float xv3 = (lane < FIN) ? x[(size_t)(nb + 3) * FIN + lane] : 0.f;

        float h0 = b1s[lane], h1 = h0, h2 = h0, h3 = h0;
#pragma unroll
        for (int i = 0; i < FIN; ++i) {
            float w = w1s[i * 32 + lane];
            h0 = fmaf(__shfl_sync(0xffffffffu, xv0, i), w, h0);
            h1 = fmaf(__shfl_sync(0xffffffffu, xv1, i), w, h1);
            h2 = fmaf(__shfl_sync(0xffffffffu, xv2, i), w, h2);
            h3 = fmaf(__shfl_sync(0xffffffffu, xv3, i), w, h3);
        }
        h0 = eluf(h0); h1 = eluf(h1); h2 = eluf(h2); h3 = eluf(h3);

        float o0 = b2s[lane], o1 = o0, o2 = o0, o3 = o0;
#pragma unroll
        for (int i = 0; i < 32; ++i) {
            float w = w2s[i * 32 + lane];
            o0 = fmaf(__shfl_sync(0xffffffffu, h0, i), w, o0);
            o1 = fmaf(__shfl_sync(0xffffffffu, h1, i), w, o1);
            o2 = fmaf(__shfl_sync(0xffffffffu, h2, i), w, o2);
            o3 = fmaf(__shfl_sync(0xffffffffu, h3, i), w, o3);
        }
        out[(size_t)(nb + 0) * 32 + lane] = eluf(o0);
        out[(size_t)(nb + 1) * 32 + lane] = eluf(o1);
        out[(size_t)(nb + 2) * 32 + lane] = eluf(o2);
        out[(size_t)(nb + 3) * 32 + lane] = eluf(o3);
    }
}

__global__ void __launch_bounds__(256) encode_all_k(
    const float* x_sv, const float* x_trk, const float* x_pfc,
    const float* svW1, const float* svb1, const float* svW2, const float* svb2,
    const float* tkW1, const float* tkb1, const float* tkW2, const float* tkb2,
    const float* pfW1, const float* pfb1, const float* pfW2, const float* pfb2,
    float* o_sv, float* o_trk, float* o_pfc)
{
    __shared__ float w1s[32 * 32];
    __shared__ float w2s[32 * 32];
    __shared__ float b1s[32], b2s[32];
    int b = blockIdx.x;
    if (b < 128)
        encode_body<14>(x_sv, svW1, svb1, svW2, svb2, o_sv, b, w1s, w2s, b1s, b2s);
    else if (b < 1152)
        encode_body<30>(x_trk, tkW1, tkb1, tkW2, tkb2, o_trk, b - 128, w1s, w2s, b1s, b2s);
    else
        encode_body<10>(x_pfc, pfW1, pfb1, pfW2, pfb2, o_pfc, b - 1152, w1s, w2s, b1s, b2s);
}

// ====== fused 32x32 linear (mode 0: (Wa-Wb)+b, mode 1: Wb) + sq output ======
__device__ __forceinline__ void lin_body(
    const float* __restrict__ in, float* __restrict__ out,
    float* __restrict__ sqout, int blk, int mode,
    const float* __restrict__ convW, const float* __restrict__ convB,
    float* ws, float* bs)
{
    int tid = threadIdx.x;
    for (int i = tid; i < 1024; i += 256)
        ws[i] = (mode == 0) ? (convW[i] - convW[1024 + i]) : convW[1024 + i];
    if (tid < 32) bs[tid] = (mode == 0) ? convB[tid] : 0.f;
    __syncthreads();

    int lane = tid & 31, wid = tid >> 5;

#pragma unroll
    for (int it = 0; it < 4; ++it) {
        int nb = blk * 128 + it * 32 + wid * 4;

        float xv0 = in[(size_t)(nb + 0) * 32 + lane];
        float xv1 = in[(size_t)(nb + 1) * 32 + lane];
        float xv2 = in[(size_t)(nb + 2) * 32 + lane];
        float xv3 = in[(size_t)(nb + 3) * 32 + lane];

        float s0 = xv0 * xv0, s1 = xv1 * xv1, s2 = xv2 * xv2, s3 = xv3 * xv3;
#pragma unroll
        for (int o = 16; o; o >>= 1) {
            s0 += __shfl_xor_sync(0xffffffffu, s0, o);
            s1 += __shfl_xor_sync(0xffffffffu, s1, o);
            s2 += __shfl_xor_sync(0xffffffffu, s2, o);
            s3 += __shfl_xor_sync(0xffffffffu, s3, o);
        }
        if (lane == 0) {
            sqout[nb + 0] = s0; sqout[nb + 1] = s1;
            sqout[nb + 2] = s2; sqout[nb + 3] = s3;
        }

        float o0 = bs[lane], o1 = o0, o2 = o0, o3 = o0;
#pragma unroll
        for (int i = 0; i < 32; ++i) {
            float w = ws[i * 32 + lane];
            o0 = fmaf(__shfl_sync(0xffffffffu, xv0, i), w, o0);
            o1 = fmaf(__shfl_sync(0xffffffffu, xv1, i), w, o1);
            o2 = fmaf(__shfl_sync(0xffffffffu, xv2, i), w, o2);
            o3 = fmaf(__shfl_sync(0xffffffffu, xv3, i), w, o3);
        }
        out[(size_t)(nb + 0) * 32 + lane] = o0;
        out[(size_t)(nb + 1) * 32 + lane] = o1;
        out[(size_t)(nb + 2) * 32 + lane] = o2;
        out[(size_t)(nb + 3) * 32 + lane] = o3;
    }
}

__global__ void __launch_bounds__(256) lin_all_k(
    const float* sv, const float* trk, const float* pfc,
    float* V1, float* U, float* V,
    float* sqV1, float* sqU, float* sqV,
    const float* convW, const float* convB)
{
    __shared__ float ws[1024];
    __shared__ float bs[32];
    int b = blockIdx.x;
    if (b < 128)        lin_body(sv,  V1, sqV1, b,        1, convW, convB, ws, bs);
    else if (b < 1152)  lin_body(trk, U,  sqU,  b - 128,  0, convW, convB, ws, bs);
    else                lin_body(pfc, V,  sqV,  b - 1152, 1, convW, convB, ws, bs);
}

__global__ void __launch_bounds__(256) lin2_k(
    const float* f1, const float* f2, float* V, float* U,
    float* sqV, float* sqU,
    const float* convW, const float* convB)
{
    __shared__ float ws[1024];
    __shared__ float bs[32];
    int b = blockIdx.x;
    if (b < 1024) lin_body(f1, V, sqV, b,        1, convW, convB, ws, bs);
    else          lin_body(f2, U, sqU, b - 1024, 0, convW, convB, ws, bs);
}

// ================= kNN: mma scoring + tau-threshold selection ===============
// 4 blocks/event (128 dsts), 256 threads = 8 warps, ONE m16 tile/warp.
// B operands staged as hi/lo[c4sel][sl][j] (66-float4 stride per c4sel slot)
// so each subtile's four fragments load as 4x LDS.128 (conflict-free:
// addr/16 mod 8 = 2*c4 + g + sl0 distinct per quarter-warp phase).
// Epilogue finalizes d2 into scores[128][66] + subset minima -> tau.
// Selection: 2 threads/dst, fixed threshold min(tau,sel7), predicated appends,
// exact u64 candidates. Stable & exact (matches jax top_k tie-break).
#define CH       64
#define SSTRIDE  66
#define C4STRIDE 66      /* float4 units per c4sel slot */
#define CAPK     10
#define SM_SCORES 0
#define SM_HILO  33792   /* 16 slots x 66 float4 = 16896 B */
#define SM_SQS   50688
#define SM_SDS   50944
#define SM_TAU   51456
#define SM_BUF   51968
#define KNN_SMEM (SM_BUF + 256 * CAPK * 8)   /* 72448 */

__device__ __forceinline__ void flush_u64(const u64* mybuf, int& cnt, u64 (&sel)[8])
{
    for (int i = 0; i < cnt; ++i) {
        u64 c = mybuf[i];
        SEL_INSERT(sel, c);
    }
    cnt = 0;
}

__global__ void __launch_bounds__(256, 3) knn_k(
                      const float* __restrict__ src_enc,
                      const float* __restrict__ dst_enc,
                      const float* __restrict__ sq_src,
                      const float* __restrict__ sq_dst,
                      const float* __restrict__ V,
                      const float* __restrict__ U,
                      float* __restrict__ out, int Ns)
{
    extern __shared__ char smraw[];
    float*  scores = (float*)(smraw + SM_SCORES);  // [128][66]
    float4* hi4    = (float4*)(smraw + SM_HILO);   // [8][66] hi, then [8][66] lo
    float*  hifl   = (float*)(smraw + SM_HILO);
    float*  sqs    = (float*)(smraw + SM_SQS);     // [64]
    float*  sds    = (float*)(smraw + SM_SDS);     // [128]
    float*  tau    = (float*)(smraw + SM_TAU);     // [128]
    u64*    buf    = (u64*)(smraw + SM_BUF);       // [256][CAPK]
    int*    idxs   = (int*)(smraw + SM_HILO);      // overlay after last MMA

    int tid  = threadIdx.x;
    int lane = tid & 31;
    int w    = tid >> 5;          // 0..7
    int e    = blockIdx.x >> 2;
    int quar = blockIdx.x & 3;
    int g    = lane >> 2;         // 0..7
    int c4   = lane & 3;          // 0..3

    const float* sbase = src_enc + (size_t)e * Ns * 32;
    int dstblk = quar * 128;
    const float* dbase = dst_enc + ((size_t)e * 512 + dstblk + w * 16) * 32;

    if (tid < 128) sds[tid] = sq_dst[(size_t)e * 512 + dstblk + tid];

    // ---- A fragments: one m16 tile (16 dsts) per warp ----
    u32 ahi[16], alo[16];
#pragma unroll
    for (int j = 0; j < 4; ++j) {
        int k = 8 * j + c4;
        tf32split(dbase[g * 32 + k],           ahi[4*j+0], alo[4*j+0]);
        tf32split(dbase[(g + 8) * 32 + k],     ahi[4*j+1], alo[4*j+1]);
        tf32split(dbase[g * 32 + k + 4],       ahi[4*j+2], alo[4*j+2]);
        tf32split(dbase[(g + 8) * 32 + k + 4], ahi[4*j+3], alo[4*j+3]);
    }
    __syncthreads();

    float sd0 = sds[w * 16 + g];
    float sd1 = sds[w * 16 + 8 + g];
    int rowA0 = (w * 16 + g) * SSTRIDE;
    int rowA1 = (w * 16 + 8 + g) * SSTRIDE;

    int myd = tid >> 1;
    int hh  = tid & 1;
    int selrow = myd * SSTRIDE;

    // per-lane fragment base pointers (const across chunks)
    const float4* bhA = hi4 + (size_t)c4 * C4STRIDE;
    const float4* bhB = hi4 + (size_t)(c4 + 4) * C4STRIDE;
    const float4* blA = bhA + 8 * C4STRIDE;
    const float4* blB = bhB + 8 * C4STRIDE;

    u64 sel[8];
#pragma unroll
    for (int k = 0; k < 8; ++k) sel[k] = ~0ull;
    int cnt = 0;
    u64* mybuf = buf + (size_t)tid * CAPK;
    unsigned buf_sa = (unsigned)__cvta_generic_to_shared(mybuf);

    // staging index for this lane's dim (lane = k)
    int stg = (lane & 7) * (C4STRIDE * 4) + (lane >> 3);

    int nch = (Ns + CH - 1) / CH;
    for (int ch = 0; ch < nch; ++ch) {
        int cbase = ch * CH;

        __syncthreads();
        // ---- stage 64 srcs into [c4sel][sl][j] layout ----
        for (int sl = w; sl < CH; sl += 8) {
            float x = sbase[(size_t)(cbase + sl) * 32 + lane];
            u32 h, l;
            tf32split(x, h, l);
            hifl[stg + sl * 4]                       = __uint_as_float(h);
            hifl[stg + sl * 4 + 8 * C4STRIDE * 4]    = __uint_as_float(l);
        }
        if (tid < CH) sqs[tid] = sq_src[(size_t)e * Ns + cbase + tid];
        __syncthreads();

        // ---- MMA + epilogue (scores + subset minima) ----
        float mn00 = 3.4e38f, mn01 = 3.4e38f, mn10 = 3.4e38f, mn11 = 3.4e38f;
#pragma unroll
        for (int st = 0; st < CH / 8; ++st) {
            int sl0 = st << 3;
            int fidx = sl0 + g;
            float4 H0 = bhA[fidx];
            float4 H1 = bhB[fidx];
            float4 L0 = blA[fidx];
            float4 L1 = blB[fidx];

            float a0 = 0.f, a1 = 0.f, a2 = 0.f, a3 = 0.f;
            // j = 0
            mma_tf32(a0, a1, a2, a3, ahi[0], ahi[1], ahi[2], ahi[3],
                     __float_as_uint(H0.x), __float_as_uint(H1.x));
            mma_tf32(a0, a1, a2, a3, ahi[0], ahi[1], ahi[2], ahi[3],
                     __float_as_uint(L0.x), __float_as_uint(L1.x));
            mma_tf32(a0, a1, a2, a3, alo[0], alo[1], alo[2], alo[3],
                     __float_as_uint(H0.x), __float_as_uint(H1.x));
            // j = 1
            mma_tf32(a0, a1, a2, a3, ahi[4], ahi[5], ahi[6], ahi[7],
                     __float_as_uint(H0.y), __float_as_uint(H1.y));
            mma_tf32(a0, a1, a2, a3, ahi[4], ahi[5], ahi[6], ahi[7],
                     __float_as_uint(L0.y), __float_as_uint(L1.y));
            mma_tf32(a0, a1, a2, a3, alo[4], alo[5], alo[6], alo[7],
                     __float_as_uint(H0.y), __float_as_uint(H1.y));
            // j = 2
            mma_tf32(a0, a1, a2, a3, ahi[8], ahi[9], ahi[10], ahi[11],
                     __float_as_uint(H0.z), __float_as_uint(H1.z));
            mma_tf32(a0, a1, a2, a3, ahi[8], ahi[9], ahi[10], ahi[11],
                     __float_as_uint(L0.z), __float_as_uint(L1.z));
            mma_tf32(a0, a1, a2, a3, alo[8], alo[9], alo[10], alo[11],
                     __float_as_uint(H0.z), __float_as_uint(H1.z));
            // j = 3
            mma_tf32(a0, a1, a2, a3, ahi[12], ahi[13], ahi[14], ahi[15],
                     __float_as_uint(H0.w), __float_as_uint(H1.w));
            mma_tf32(a0, a1, a2, a3, ahi[12], ahi[13], ahi[14], ahi[15],
                     __float_as_uint(L0.w), __float_as_uint(L1.w));
            mma_tf32(a0, a1, a2, a3, alo[12], alo[13], alo[14], alo[15],
                     __float_as_uint(H0.w), __float_as_uint(H1.w));

            float2 sqp = *(const float2*)(sqs + sl0 + 2 * c4);
            int col = sl0 + 2 * c4;
            float d00 = fmaxf(fmaf(-2.f, a0, sd0 + sqp.x), 0.f);
            float d01 = fmaxf(fmaf(-2.f, a1, sd0 + sqp.y), 0.f);
            float d10 = fmaxf(fmaf(-2.f, a2, sd1 + sqp.x), 0.f);
            float d11 = fmaxf(fmaf(-2.f, a3, sd1 + sqp.y), 0.f);
            mn00 = fminf(mn00, d00); mn01 = fminf(mn01, d01);
            mn10 = fminf(mn10, d10); mn11 = fminf(mn11, d11);
            *(float2*)(scores + rowA0 + col) = make_float2(d00, d01);
            *(float2*)(scores + rowA1 + col) = make_float2(d10, d11);
        }
        // tau per row: max over quad of the 2 slot-minima (8 disjoint subsets)
        {
            float m0 = fmaxf(mn00, mn01);
            m0 = fmaxf(m0, __shfl_xor_sync(0xffffffffu, m0, 1));
            m0 = fmaxf(m0, __shfl_xor_sync(0xffffffffu, m0, 2));
            float m1 = fmaxf(mn10, mn11);
            m1 = fmaxf(m1, __shfl_xor_sync(0xffffffffu, m1, 1));
            m1 = fmaxf(m1, __shfl_xor_sync(0xffffffffu, m1, 2));
            if (c4 == 0) {
                tau[w * 16 + g]     = m0;
                tau[w * 16 + 8 + g] = m1;
            }
        }
        __syncthreads();

        // ---- selection: fixed threshold, predicated appends ----
        {
            float tf_ = tau[myd];
            u64 tu = ((u64)(__float_as_uint(tf_) + 1u)) << 32;  // accept <= tau
            u64 t = (tu < sel[7]) ? tu : sel[7];

            for (int cg = 0; cg < 32; cg += 4) {
                int c0i = 2 * cg + hh;
                float v0 = scores[selrow + c0i];
                float v1 = scores[selrow + c0i + 2];
                float v2 = scores[selrow + c0i + 4];
                float v3 = scores[selrow + c0i + 6];
                u64 p0 = ((u64)__float_as_uint(v0) << 32) | (u32)(cbase + c0i);
                u64 p1 = ((u64)__float_as_uint(v1) << 32) | (u32)(cbase + c0i + 2);
                u64 p2 = ((u64)__float_as_uint(v2) << 32) | (u32)(cbase + c0i + 4);
                u64 p3 = ((u64)__float_as_uint(v3) << 32) | (u32)(cbase + c0i + 6);

                asm volatile("{.reg .pred p; setp.lt.u64 p, %1, %2; @p st.shared.b64 [%0], %1;}"
                    :: "r"(buf_sa + (unsigned)cnt * 8u), "l"(p0), "l"(t) : "memory");
                cnt += (p0 < t) ? 1 : 0;
                asm volatile("{.reg .pred p; setp.lt.u64 p, %1, %2; @p st.shared.b64 [%0], %1;}"
                    :: "r"(buf_sa + (unsigned)cnt * 8u), "l"(p1), "l"(t) : "memory");
                cnt += (p1 < t) ? 1 : 0;
                asm volatile("{.reg .pred p; setp.lt.u64 p, %1, %2; @p st.shared.b64 [%0], %1;}"
                    :: "r"(buf_sa + (unsigned)cnt * 8u), "l"(p2), "l"(t) : "memory");
                cnt += (p2 < t) ? 1 : 0;
                asm volatile("{.reg .pred p; setp.lt.u64 p, %1, %2; @p st.shared.b64 [%0], %1;}"
                    :: "r"(buf_sa + (unsigned)cnt * 8u), "l"(p3), "l"(t) : "memory");
                cnt += (p3 < t) ? 1 : 0;

                if (__any_sync(0xffffffffu, cnt >= CAPK - 4)) {
                    flush_u64(mybuf, cnt, sel);
                }
            }
            flush_u64(mybuf, cnt, sel);   // per-chunk drain -> sel7 tightens
        }
    }

    // ---- dump per-thread lists, 2-way exact merge ----
#pragma unroll
    for (int k = 0; k < 8; ++k) mybuf[k] = sel[k];
    __syncthreads();

    if (tid < 128) {
        u64 m[8];
        const u64* l0 = buf + (size_t)(2 * tid) * CAPK;
        const u64* l1 = buf + (size_t)(2 * tid + 1) * CAPK;
#pragma unroll
        for (int k = 0; k < 8; ++k) m[k] = l0[k];
#pragma unroll
        for (int k = 0; k < 8; ++k) {
            u64 c = l1[k];
            SEL_INSERT(m, c);
        }
#pragma unroll
        for (int k = 0; k < 8; ++k)
            idxs[tid * 8 + k] = (int)(u32)m[k];
    }
    __syncthreads();

    // ---- aggregation: warp per dst, coalesced V gathers ----
    const float* Ve = V + (size_t)e * Ns * 32;
    for (int dd = w; dd < 128; dd += 8) {
        int dg = e * 512 + dstblk + dd;
        float mx = -3.4e38f;
#pragma unroll
        for (int k = 0; k < KNN; ++k) {
            int s = idxs[dd * 8 + k];
            mx = fmaxf(mx, Ve[s * 32 + lane]);
        }
        out[(size_t)dg * 32 + lane] = eluf(U[(size_t)dg * 32 + lane] + mx);
    }
}

// ---------------- mean pool + head MLP + sigmoid -----------------------------
__global__ void pool_k(const float* __restrict__ f3,
                       const float* __restrict__ W1, const float* __restrict__ b1,
                       const float* __restrict__ W2, const float* __restrict__ b2,
                       float* __restrict__ out, int out_size)
{
    int e = blockIdx.x;
    int tid = threadIdx.x;
    int j = tid & 31, g = tid >> 5;
    const float* base = f3 + (size_t)e * 512 * 32;
    float acc = 0.f;
    for (int r = g; r < 512; r += 8) acc += base[r * 32 + j];
    __shared__ float red[8][32];
    red[g][j] = acc;
    __syncthreads();
    if (tid < 32) {
        float s = 0.f;
#pragma unroll
        for (int gg = 0; gg < 8; ++gg) s += red[gg][tid];
        float pooled = s * (1.f / 512.f);
        float h = b1[tid];
#pragma unroll
        for (int i = 0; i < 32; ++i)
            h = fmaf(__shfl_sync(0xffffffffu, pooled, i), W1[i * 32 + tid], h);
        h = eluf(h);
        float t = h * W2[tid];
#pragma unroll
        for (int o = 16; o; o >>= 1) t += __shfl_down_sync(0xffffffffu, t, o);
        if (tid == 0) {
            float prob = 1.f / (1.f + expf(-(t + b2[0])));
            out[e] = prob;
            if (out_size == 2 * BB) out[BB + e] = (float)e;
            else if (out_size == 3 * BB) ((long long*)(out + BB))[e] = (long long)e;
        }
    }
}

// ---------------- launch ------------------------------------------------------
extern "C" void kernel_launch(void* const* d_in, const int* in_sizes, int n_in,
                              void* d_out, int out_size)
{
    const float* x_sv   = (const float*)d_in[0];
    const float* x_trk  = (const float*)d_in[1];
    const float* x_pfc  = (const float*)d_in[2];
    const float* sv_W1  = (const float*)d_in[6];
    const float* sv_b1  = (const float*)d_in[7];
    const float* sv_W2  = (const float*)d_in[8];
    const float* sv_b2  = (const float*)d_in[9];
    const float* trk_W1 = (const float*)d_in[10];
    const float* trk_b1 = (const float*)d_in[11];
    const float* trk_W2 = (const float*)d_in[12];
    const float* trk_b2 = (const float*)d_in[13];
    const float* pfc_W1 = (const float*)d_in[14];
    const float* pfc_b1 = (const float*)d_in[15];
    const float* pfc_W2 = (const float*)d_in[16];
    const float* pfc_b2 = (const float*)d_in[17];
    const float* conv_W = (const float*)d_in[18];
    const float* conv_b = (const float*)d_in[19];
    const float* out_W1 = (const float*)d_in[20];
    const float* out_b1 = (const float*)d_in[21];
    const float* out_W2 = (const float*)d_in[22];
    const float* out_b2 = (const float*)d_in[23];
    float* out = (float*)d_out;

    float *sv, *trk, *pfc, *U, *V, *V1, *f1, *f2, *f3, *sqV1, *sqV, *sqU;
    cudaGetSymbolAddress((void**)&sv,  g_sv);
    cudaGetSymbolAddress((void**)&trk, g_trk);
    cudaGetSymbolAddress((void**)&pfc, g_pfc);
    cudaGetSymbolAddress((void**)&U,   g_U);
    cudaGetSymbolAddress((void**)&V,   g_V);
    cudaGetSymbolAddress((void**)&V1,  g_V1);
    cudaGetSymbolAddress((void**)&f1,  g_f1);
    cudaGetSymbolAddress((void**)&f2,  g_f2);
    cudaGetSymbolAddress((void**)&f3,  g_f3);
    cudaGetSymbolAddress((void**)&sqV1, g_sqV1);
    cudaGetSymbolAddress((void**)&sqV,  g_sqV);
    cudaGetSymbolAddress((void**)&sqU,  g_sqU);

    cudaFuncSetAttribute(knn_k, cudaFuncAttributeMaxDynamicSharedMemorySize, KNN_SMEM);

    encode_all_k<<<2176, 256>>>(x_sv, x_trk, x_pfc,
                                sv_W1, sv_b1, sv_W2, sv_b2,
                                trk_W1, trk_b1, trk_W2, trk_b2,
                                pfc_W1, pfc_b1, pfc_W2, pfc_b2,
                                sv, trk, pfc);
    lin_all_k<<<2176, 256>>>(sv, trk, pfc, V1, U, V, sqV1, sqU, sqV, conv_W, conv_b);
    knn_k<<<BB * 4, 256, KNN_SMEM>>>(sv,  trk, sqV1, sqU, V1, U, f1, N_SV);
    knn_k<<<BB * 4, 256, KNN_SMEM>>>(pfc, trk, sqV,  sqU, V,  U, f2, N_PFC);
    lin2_k<<<2048, 256>>>(f1, f2, V, U, sqV, sqU, conv_W, conv_b);
    knn_k<<<BB * 4, 256, KNN_SMEM>>>(f1, f2, sqV, sqU, V, U, f3, N_TRK);
    pool_k<<<BB, 256>>>(f3, out_W1, out_b1, out_W2, out_b2, out, out_size);
}